// round 1
// baseline (speedup 1.0000x reference)
#include <cuda_runtime.h>
#include <cstddef>

// Problem constants
#define BB   2
#define SS   2048
#define DD   512
#define HH   8
#define DEP  64
#define BSD  (BB*SS*DD)                    // 2,097,152 floats (output)
// attention weights: BB*HH*SS*SS = 67,108,864 floats

// ---------------- scratch (device globals; no allocation allowed) ----------------
__device__ float g_q[BB*HH*SS*DEP];   // [B,H,S,64] projected Q
__device__ float g_k[BB*HH*SS*DEP];   // [B,H,S,64] projected K
__device__ float g_v[BB*HH*SS*DEP];   // [B,H,S,64] projected V
__device__ float g_c[BB*SS*DD];       // [B,S,D] concat(attention)

// =================================================================================
// GEMM: out[M=4096,N=512] = X[4096,512] @ W[512,512] + bias
// mode 0: scatter to head-split layout [B,H,S,64]; mode 1: flat [M,N]
// 128x128 tile, 256 threads, 8x8 per thread, K-chunks of 16.
// =================================================================================
__global__ __launch_bounds__(256) void gemm128(const float* __restrict__ X,
                                               const float* __restrict__ W,
                                               const float* __restrict__ bias,
                                               float* __restrict__ out, int mode)
{
    __shared__ float Xs[16*132];   // [k][m], padded
    __shared__ float Wt[16*132];   // [k][n], padded
    const int t  = threadIdx.x;
    const int tx = t & 15, ty = t >> 4;
    const int m0 = blockIdx.x * 128, n0 = blockIdx.y * 128;

    float acc[8][8];
    #pragma unroll
    for (int i = 0; i < 8; i++)
        #pragma unroll
        for (int j = 0; j < 8; j++) acc[i][j] = 0.f;

    for (int kb = 0; kb < DD; kb += 16) {
        __syncthreads();
        #pragma unroll
        for (int i = 0; i < 8; i++) {
            int idx = t + i*256;
            int k = idx & 15, m = idx >> 4;
            Xs[k*132 + m] = X[(size_t)(m0 + m)*DD + kb + k];
        }
        #pragma unroll
        for (int i = 0; i < 8; i++) {
            int idx = t + i*256;
            int n = idx & 127, k = idx >> 7;
            Wt[k*132 + n] = W[(size_t)(kb + k)*DD + n0 + n];
        }
        __syncthreads();
        #pragma unroll
        for (int k = 0; k < 16; k++) {
            float4 a0 = *(const float4*)&Xs[k*132 + ty*8];
            float4 a1 = *(const float4*)&Xs[k*132 + ty*8 + 4];
            float4 b0 = *(const float4*)&Wt[k*132 + tx*8];
            float4 b1 = *(const float4*)&Wt[k*132 + tx*8 + 4];
            float a[8] = {a0.x,a0.y,a0.z,a0.w,a1.x,a1.y,a1.z,a1.w};
            float b[8] = {b0.x,b0.y,b0.z,b0.w,b1.x,b1.y,b1.z,b1.w};
            #pragma unroll
            for (int i = 0; i < 8; i++)
                #pragma unroll
                for (int j = 0; j < 8; j++) acc[i][j] += a[i]*b[j];
        }
    }

    #pragma unroll
    for (int i = 0; i < 8; i++) {
        int m = m0 + ty*8 + i;
        int b_ = m >> 11, s = m & (SS - 1);
        #pragma unroll
        for (int j = 0; j < 8; j++) {
            int n = n0 + tx*8 + j;
            float v = acc[i][j] + bias[n];
            if (mode == 0) {
                int h = n >> 6, d = n & 63;
                out[(((size_t)(b_*HH + h)*SS + s) << 6) + d] = v;
            } else {
                out[(size_t)m*DD + n] = v;
            }
        }
    }
}

// =================================================================================
// Fused causal attention with relative position bias.
// One CTA = (b, h, 64-query tile). 256 threads.
// Phase 1: logits l = (q·k + q·E[S-1-q+k]) / 8 for k<=q  (else -1e30),
//          raw l streamed to the attention-weight output region (scratch in-place),
//          flash-style per-row (max,sum) maintained in smem.
// Phase 2: read raw l back (L2 hot), write normalized weights, accumulate P@V,
//          zero-fill the strictly-upper columns, store O into concat buffer.
// Dynamic smem layout (floats):
//   [0,4160)       Qs   64 x 65
//   [4160,8512)    B1   K tile 64x65 (phase1) / V tile 64x68 (phase2)
//   [8512,16832)   B2   E window 128x65 (phase1) / W tile 64x68 (phase2)
//   [16832,16896)  rm   row max
//   [16896,16960)  rs   row sumexp                 total = 67840 bytes
// =================================================================================
__global__ __launch_bounds__(256) void attn_kernel(const float* __restrict__ E,
                                                   float* __restrict__ attn)
{
    extern __shared__ float sm[];
    float* Qs = sm;
    float* B1 = sm + 4160;
    float* B2 = sm + 8512;
    float* rm = sm + 16832;
    float* rs = sm + 16896;

    const int t  = threadIdx.x;
    const int qt = (int)gridDim.x - 1 - (int)blockIdx.x;   // big tiles first
    const int q0 = qt * 64;
    const int h  = blockIdx.y, b = blockIdx.z;
    const int bh = b*HH + h;
    const float* qb = g_q + (size_t)bh*SS*DEP;
    const float* kb = g_k + (size_t)bh*SS*DEP;
    const float* vb = g_v + (size_t)bh*SS*DEP;
    float* arow_base = attn + ((size_t)bh*SS + q0) * SS;

    for (int idx = t; idx < 64*DEP; idx += 256) {
        int i = idx >> 6, d = idx & 63;
        Qs[i*65 + d] = qb[(size_t)(q0 + i)*DEP + d];
    }
    if (t < 64) { rm[t] = -1e30f; rs[t] = 0.f; }
    __syncthreads();

    const int ql = t >> 2, ksub = t & 3;
    const int nch = qt + 1;

    int offK[16], offE[16];
    #pragma unroll
    for (int j = 0; j < 16; j++) {
        int kl = ksub + 4*j;
        offK[j] = kl*65;
        offE[j] = (63 - ql + kl)*65;   // E row e0 + (63-ql+kl) == S-1-q+k
    }

    // ---------------- phase 1: logits + row stats ----------------
    for (int kt = 0; kt < nch; ++kt) {
        const int k0 = kt*64;
        for (int idx = t; idx < 64*DEP; idx += 256) {
            int i = idx >> 6, d = idx & 63;
            B1[i*65 + d] = kb[(size_t)(k0 + i)*DEP + d];
        }
        const int e0 = SS - 64 - q0 + k0;   // always >= 0
        for (int idx = t; idx < 128*DEP; idx += 256) {
            int r = idx >> 6, d = idx & 63;
            int er = e0 + r;
            B2[r*65 + d] = (er < SS) ? E[(size_t)er*DEP + d] : 0.f;
        }
        __syncthreads();

        float acc[16];
        #pragma unroll
        for (int j = 0; j < 16; j++) acc[j] = 0.f;
        const float* qr = Qs + ql*65;
        #pragma unroll 4
        for (int d = 0; d < DEP; ++d) {
            float qd = qr[d];
            #pragma unroll
            for (int j = 0; j < 16; j++)
                acc[j] += qd * (B1[offK[j] + d] + B2[offE[j] + d]);
        }

        float lmax = -1e30f;
        #pragma unroll
        for (int j = 0; j < 16; j++) {
            int kg = k0 + ksub + 4*j;
            float l = (kg <= q0 + ql) ? acc[j]*0.125f : -1e30f;
            acc[j] = l;
            lmax = fmaxf(lmax, l);
        }
        float lsum = 0.f;
        #pragma unroll
        for (int j = 0; j < 16; j++) lsum += __expf(acc[j] - lmax);

        float* ar = arow_base + (size_t)ql*SS + k0;
        #pragma unroll
        for (int j = 0; j < 16; j++) ar[ksub + 4*j] = acc[j];

        #pragma unroll
        for (int off = 1; off < 4; off <<= 1) {
            float om = __shfl_xor_sync(0xffffffffu, lmax, off);
            float os = __shfl_xor_sync(0xffffffffu, lsum, off);
            float nm = fmaxf(lmax, om);
            lsum = lsum*__expf(lmax - nm) + os*__expf(om - nm);
            lmax = nm;
        }
        if (ksub == 0) {
            float mo = rm[ql];
            float nm = fmaxf(mo, lmax);
            rs[ql] = rs[ql]*__expf(mo - nm) + lsum*__expf(lmax - nm);
            rm[ql] = nm;
        }
        __syncthreads();
    }

    const float rmax = rm[ql];
    const float rinv = 1.f / rs[ql];

    // ---------------- phase 2: normalize weights + P @ V ----------------
    float* Vs = B1;   // pitch 68
    float* Ws = B2;   // pitch 68
    float Ov[16];
    #pragma unroll
    for (int i = 0; i < 16; i++) Ov[i] = 0.f;

    for (int kt = 0; kt < nch; ++kt) {
        const int k0 = kt*64;
        __syncthreads();   // previous-iteration Vs/Ws reads complete
        for (int idx = t; idx < 64*DEP; idx += 256) {
            int i = idx >> 6, d = idx & 63;
            Vs[i*68 + d] = vb[(size_t)(k0 + i)*DEP + d];
        }
        float* ar = arow_base + (size_t)ql*SS + k0;
        #pragma unroll
        for (int j = 0; j < 16; j++) {
            int kl = ksub + 4*j;
            float w = __expf(ar[kl] - rmax) * rinv;   // masked entries -> exact 0
            ar[kl] = w;
            Ws[ql*68 + kl] = w;
        }
        __syncthreads();
        #pragma unroll 2
        for (int kk = 0; kk < 64; ++kk) {
            float wv = Ws[ql*68 + kk];
            const float4* vr = (const float4*)(Vs + kk*68 + ksub*16);
            float4 v0 = vr[0], v1 = vr[1], v2 = vr[2], v3 = vr[3];
            Ov[0]  += wv*v0.x; Ov[1]  += wv*v0.y; Ov[2]  += wv*v0.z; Ov[3]  += wv*v0.w;
            Ov[4]  += wv*v1.x; Ov[5]  += wv*v1.y; Ov[6]  += wv*v1.z; Ov[7]  += wv*v1.w;
            Ov[8]  += wv*v2.x; Ov[9]  += wv*v2.y; Ov[10] += wv*v2.z; Ov[11] += wv*v2.w;
            Ov[12] += wv*v3.x; Ov[13] += wv*v3.y; Ov[14] += wv*v3.z; Ov[15] += wv*v3.w;
        }
    }

    // zero-fill strictly-upper tail columns [nch*64, S)
    const int kstart = nch*64;
    if (kstart < SS) {
        const int len4 = (SS - kstart) >> 2;
        const int tot = 64 * len4;
        for (int idx = t; idx < tot; idx += 256) {
            int row = idx / len4, c = idx - row*len4;
            ((float4*)(arow_base + (size_t)row*SS + kstart))[c] =
                make_float4(0.f, 0.f, 0.f, 0.f);
        }
    }

    // O -> concat buffer [B,S,D], d-major within head
    {
        float* cr = g_c + ((size_t)b*SS + q0 + ql)*DD + h*64 + ksub*16;
        float4* c4 = (float4*)cr;
        c4[0] = make_float4(Ov[0],  Ov[1],  Ov[2],  Ov[3]);
        c4[1] = make_float4(Ov[4],  Ov[5],  Ov[6],  Ov[7]);
        c4[2] = make_float4(Ov[8],  Ov[9],  Ov[10], Ov[11]);
        c4[3] = make_float4(Ov[12], Ov[13], Ov[14], Ov[15]);
    }
}

// =================================================================================
// launch
// inputs: 0 v_in, 1 k_in, 2 q_in, 3 mask(unused), 4 Wq, 5 bq, 6 Wk, 7 bk,
//         8 Wv, 9 bv, 10 Wo, 11 bo, 12 E
// output: [output (B*S*D floats)] ++ [attention_weights (B*H*S*S floats)]
// =================================================================================
extern "C" void kernel_launch(void* const* d_in, const int* in_sizes, int n_in,
                              void* d_out, int out_size)
{
    (void)in_sizes; (void)n_in; (void)out_size;
    const float* v_in = (const float*)d_in[0];
    const float* k_in = (const float*)d_in[1];
    const float* q_in = (const float*)d_in[2];
    const float* Wq   = (const float*)d_in[4];
    const float* bq   = (const float*)d_in[5];
    const float* Wk   = (const float*)d_in[6];
    const float* bk   = (const float*)d_in[7];
    const float* Wv   = (const float*)d_in[8];
    const float* bv   = (const float*)d_in[9];
    const float* Wo   = (const float*)d_in[10];
    const float* bo   = (const float*)d_in[11];
    const float* E    = (const float*)d_in[12];

    float* out  = (float*)d_out;
    float* attn = out + (size_t)BSD;

    float *gq, *gk, *gv, *gc;
    cudaGetSymbolAddress((void**)&gq, g_q);
    cudaGetSymbolAddress((void**)&gk, g_k);
    cudaGetSymbolAddress((void**)&gv, g_v);
    cudaGetSymbolAddress((void**)&gc, g_c);

    cudaFuncSetAttribute(attn_kernel,
                         cudaFuncAttributeMaxDynamicSharedMemorySize, 67840);

    dim3 pg(32, 4);   // 4096/128 x 512/128
    gemm128<<<pg, 256>>>(q_in, Wq, bq, gq, 0);
    gemm128<<<pg, 256>>>(k_in, Wk, bk, gk, 0);
    gemm128<<<pg, 256>>>(v_in, Wv, bv, gv, 0);
    attn_kernel<<<dim3(32, HH, BB), 256, 67840>>>(E, attn);
    gemm128<<<pg, 256>>>(gc, Wo, bo, out, 1);
}

// round 2
// speedup vs baseline: 1.0141x; 1.0141x over previous
#include <cuda_runtime.h>
#include <cstddef>

// Problem constants
#define BB   2
#define SS   2048
#define DD   512
#define HH   8
#define DEP  64
#define BSD  (BB*SS*DD)                    // 2,097,152 floats (output)
// attention weights: BB*HH*SS*SS = 67,108,864 floats

// ---------------- scratch (device globals; no allocation allowed) ----------------
__device__ float g_q[BB*HH*SS*DEP];   // [B,H,S,64] projected Q
__device__ float g_k[BB*HH*SS*DEP];   // [B,H,S,64] projected K
__device__ float g_v[BB*HH*SS*DEP];   // [B,H,S,64] projected V
__device__ float g_c[BB*SS*DD];       // [B,S,D] concat(attention)

// =================================================================================
// GEMM: out[M=4096,N=512] = X[4096,512] @ W[512,512] + bias
// mode 0: scatter to head-split layout [B,H,S,64]; mode 1: flat [M,N]
// 128x128 tile, 256 threads, 8x8 per thread, K-chunks of 16.
// =================================================================================
__global__ __launch_bounds__(256) void gemm128(const float* __restrict__ X,
                                               const float* __restrict__ W,
                                               const float* __restrict__ bias,
                                               float* __restrict__ out, int mode)
{
    __shared__ float Xs[16*132];   // [k][m], padded
    __shared__ float Wt[16*132];   // [k][n], padded
    const int t  = threadIdx.x;
    const int tx = t & 15, ty = t >> 4;
    const int m0 = blockIdx.x * 128, n0 = blockIdx.y * 128;

    float acc[8][8];
    #pragma unroll
    for (int i = 0; i < 8; i++)
        #pragma unroll
        for (int j = 0; j < 8; j++) acc[i][j] = 0.f;

    for (int kb = 0; kb < DD; kb += 16) {
        __syncthreads();
        #pragma unroll
        for (int i = 0; i < 8; i++) {
            int idx = t + i*256;
            int k = idx & 15, m = idx >> 4;
            Xs[k*132 + m] = X[(size_t)(m0 + m)*DD + kb + k];
        }
        #pragma unroll
        for (int i = 0; i < 8; i++) {
            int idx = t + i*256;
            int n = idx & 127, k = idx >> 7;
            Wt[k*132 + n] = W[(size_t)(kb + k)*DD + n0 + n];
        }
        __syncthreads();
        #pragma unroll
        for (int k = 0; k < 16; k++) {
            float4 a0 = *(const float4*)&Xs[k*132 + ty*8];
            float4 a1 = *(const float4*)&Xs[k*132 + ty*8 + 4];
            float4 b0 = *(const float4*)&Wt[k*132 + tx*8];
            float4 b1 = *(const float4*)&Wt[k*132 + tx*8 + 4];
            float a[8] = {a0.x,a0.y,a0.z,a0.w,a1.x,a1.y,a1.z,a1.w};
            float b[8] = {b0.x,b0.y,b0.z,b0.w,b1.x,b1.y,b1.z,b1.w};
            #pragma unroll
            for (int i = 0; i < 8; i++)
                #pragma unroll
                for (int j = 0; j < 8; j++) acc[i][j] += a[i]*b[j];
        }
    }

    #pragma unroll
    for (int i = 0; i < 8; i++) {
        int m = m0 + ty*8 + i;
        int b_ = m >> 11, s = m & (SS - 1);
        #pragma unroll
        for (int j = 0; j < 8; j++) {
            int n = n0 + tx*8 + j;
            float v = acc[i][j] + bias[n];
            if (mode == 0) {
                int h = n >> 6, d = n & 63;
                out[(((size_t)(b_*HH + h)*SS + s) << 6) + d] = v;
            } else {
                out[(size_t)m*DD + n] = v;
            }
        }
    }
}

// =================================================================================
// Fused causal attention with relative position bias.
// One CTA = (b, h, 64-query tile). 256 threads.
// Phase 1: logits l = (q·k + q·E[S-1-q+k]) / 8 for k<=q  (else -1e30),
//          raw l streamed to the attention-weight output region (scratch in-place),
//          flash-style per-row (max,sum) maintained in smem.
// Phase 2: read raw l back (L2 hot), write normalized weights, accumulate P@V,
//          zero-fill the strictly-upper columns, store O into concat buffer.
// Dynamic smem layout (floats):
//   [0,4160)       Qs   64 x 65
//   [4160,8512)    B1   K tile 64x65 (phase1) / V tile 64x68 (phase2)
//   [8512,16832)   B2   E window 128x65 (phase1) / W tile 64x68 (phase2)
//   [16832,16896)  rm   row max
//   [16896,16960)  rs   row sumexp                 total = 67840 bytes
// =================================================================================
__global__ __launch_bounds__(256) void attn_kernel(const float* __restrict__ E,
                                                   float* __restrict__ attn)
{
    extern __shared__ float sm[];
    float* Qs = sm;
    float* B1 = sm + 4160;
    float* B2 = sm + 8512;
    float* rm = sm + 16832;
    float* rs = sm + 16896;

    const int t  = threadIdx.x;
    const int qt = (int)gridDim.x - 1 - (int)blockIdx.x;   // big tiles first
    const int q0 = qt * 64;
    const int h  = blockIdx.y, b = blockIdx.z;
    const int bh = b*HH + h;
    const float* qb = g_q + (size_t)bh*SS*DEP;
    const float* kb = g_k + (size_t)bh*SS*DEP;
    const float* vb = g_v + (size_t)bh*SS*DEP;
    float* arow_base = attn + ((size_t)bh*SS + q0) * SS;

    for (int idx = t; idx < 64*DEP; idx += 256) {
        int i = idx >> 6, d = idx & 63;
        Qs[i*65 + d] = qb[(size_t)(q0 + i)*DEP + d];
    }
    if (t < 64) { rm[t] = -1e30f; rs[t] = 0.f; }
    __syncthreads();

    const int ql = t >> 2, ksub = t & 3;
    const int nch = qt + 1;

    int offK[16], offE[16];
    #pragma unroll
    for (int j = 0; j < 16; j++) {
        int kl = ksub + 4*j;
        offK[j] = kl*65;
        offE[j] = (63 - ql + kl)*65;   // E row e0 + (63-ql+kl) == S-1-q+k
    }

    // ---------------- phase 1: logits + row stats ----------------
    for (int kt = 0; kt < nch; ++kt) {
        const int k0 = kt*64;
        for (int idx = t; idx < 64*DEP; idx += 256) {
            int i = idx >> 6, d = idx & 63;
            B1[i*65 + d] = kb[(size_t)(k0 + i)*DEP + d];
        }
        const int e0 = SS - 64 - q0 + k0;   // always >= 0
        for (int idx = t; idx < 128*DEP; idx += 256) {
            int r = idx >> 6, d = idx & 63;
            int er = e0 + r;
            B2[r*65 + d] = (er < SS) ? E[(size_t)er*DEP + d] : 0.f;
        }
        __syncthreads();

        float acc[16];
        #pragma unroll
        for (int j = 0; j < 16; j++) acc[j] = 0.f;
        const float* qr = Qs + ql*65;
        #pragma unroll 4
        for (int d = 0; d < DEP; ++d) {
            float qd = qr[d];
            #pragma unroll
            for (int j = 0; j < 16; j++)
                acc[j] += qd * (B1[offK[j] + d] + B2[offE[j] + d]);
        }

        float lmax = -1e30f;
        #pragma unroll
        for (int j = 0; j < 16; j++) {
            int kg = k0 + ksub + 4*j;
            float l = (kg <= q0 + ql) ? acc[j]*0.125f : -1e30f;
            acc[j] = l;
            lmax = fmaxf(lmax, l);
        }
        float lsum = 0.f;
        #pragma unroll
        for (int j = 0; j < 16; j++) lsum += __expf(acc[j] - lmax);

        float* ar = arow_base + (size_t)ql*SS + k0;
        #pragma unroll
        for (int j = 0; j < 16; j++) ar[ksub + 4*j] = acc[j];

        #pragma unroll
        for (int off = 1; off < 4; off <<= 1) {
            float om = __shfl_xor_sync(0xffffffffu, lmax, off);
            float os = __shfl_xor_sync(0xffffffffu, lsum, off);
            float nm = fmaxf(lmax, om);
            lsum = lsum*__expf(lmax - nm) + os*__expf(om - nm);
            lmax = nm;
        }
        if (ksub == 0) {
            float mo = rm[ql];
            float nm = fmaxf(mo, lmax);
            rs[ql] = rs[ql]*__expf(mo - nm) + lsum*__expf(lmax - nm);
            rm[ql] = nm;
        }
        __syncthreads();
    }

    const float rmax = rm[ql];
    const float rinv = 1.f / rs[ql];

    // ---------------- phase 2: normalize weights + P @ V ----------------
    float* Vs = B1;   // pitch 68
    float* Ws = B2;   // pitch 68
    float Ov[16];
    #pragma unroll
    for (int i = 0; i < 16; i++) Ov[i] = 0.f;

    for (int kt = 0; kt < nch; ++kt) {
        const int k0 = kt*64;
        __syncthreads();   // previous-iteration Vs/Ws reads complete
        for (int idx = t; idx < 64*DEP; idx += 256) {
            int i = idx >> 6, d = idx & 63;
            Vs[i*68 + d] = vb[(size_t)(k0 + i)*DEP + d];
        }
        float* ar = arow_base + (size_t)ql*SS + k0;
        #pragma unroll
        for (int j = 0; j < 16; j++) {
            int kl = ksub + 4*j;
            float w = __expf(ar[kl] - rmax) * rinv;   // masked entries -> exact 0
            ar[kl] = w;
            Ws[ql*68 + kl] = w;
        }
        __syncthreads();
        #pragma unroll 2
        for (int kk = 0; kk < 64; ++kk) {
            float wv = Ws[ql*68 + kk];
            const float4* vr = (const float4*)(Vs + kk*68 + ksub*16);
            float4 v0 = vr[0], v1 = vr[1], v2 = vr[2], v3 = vr[3];
            Ov[0]  += wv*v0.x; Ov[1]  += wv*v0.y; Ov[2]  += wv*v0.z; Ov[3]  += wv*v0.w;
            Ov[4]  += wv*v1.x; Ov[5]  += wv*v1.y; Ov[6]  += wv*v1.z; Ov[7]  += wv*v1.w;
            Ov[8]  += wv*v2.x; Ov[9]  += wv*v2.y; Ov[10] += wv*v2.z; Ov[11] += wv*v2.w;
            Ov[12] += wv*v3.x; Ov[13] += wv*v3.y; Ov[14] += wv*v3.z; Ov[15] += wv*v3.w;
        }
    }

    // zero-fill strictly-upper tail columns [nch*64, S)
    const int kstart = nch*64;
    if (kstart < SS) {
        const int len4 = (SS - kstart) >> 2;
        const int tot = 64 * len4;
        for (int idx = t; idx < tot; idx += 256) {
            int row = idx / len4, c = idx - row*len4;
            ((float4*)(arow_base + (size_t)row*SS + kstart))[c] =
                make_float4(0.f, 0.f, 0.f, 0.f);
        }
    }

    // O -> concat buffer [B,S,D], d-major within head
    {
        float* cr = g_c + ((size_t)b*SS + q0 + ql)*DD + h*64 + ksub*16;
        float4* c4 = (float4*)cr;
        c4[0] = make_float4(Ov[0],  Ov[1],  Ov[2],  Ov[3]);
        c4[1] = make_float4(Ov[4],  Ov[5],  Ov[6],  Ov[7]);
        c4[2] = make_float4(Ov[8],  Ov[9],  Ov[10], Ov[11]);
        c4[3] = make_float4(Ov[12], Ov[13], Ov[14], Ov[15]);
    }
}

// =================================================================================
// launch
// inputs: 0 v_in, 1 k_in, 2 q_in, 3 mask(unused), 4 Wq, 5 bq, 6 Wk, 7 bk,
//         8 Wv, 9 bv, 10 Wo, 11 bo, 12 E
// output: [output (B*S*D floats)] ++ [attention_weights (B*H*S*S floats)]
// =================================================================================
extern "C" void kernel_launch(void* const* d_in, const int* in_sizes, int n_in,
                              void* d_out, int out_size)
{
    (void)in_sizes; (void)n_in; (void)out_size;
    const float* v_in = (const float*)d_in[0];
    const float* k_in = (const float*)d_in[1];
    const float* q_in = (const float*)d_in[2];
    const float* Wq   = (const float*)d_in[4];
    const float* bq   = (const float*)d_in[5];
    const float* Wk   = (const float*)d_in[6];
    const float* bk   = (const float*)d_in[7];
    const float* Wv   = (const float*)d_in[8];
    const float* bv   = (const float*)d_in[9];
    const float* Wo   = (const float*)d_in[10];
    const float* bo   = (const float*)d_in[11];
    const float* E    = (const float*)d_in[12];

    float* out  = (float*)d_out;
    float* attn = out + (size_t)BSD;

    float *gq, *gk, *gv, *gc;
    cudaGetSymbolAddress((void**)&gq, g_q);
    cudaGetSymbolAddress((void**)&gk, g_k);
    cudaGetSymbolAddress((void**)&gv, g_v);
    cudaGetSymbolAddress((void**)&gc, g_c);

    cudaFuncSetAttribute(attn_kernel,
                         cudaFuncAttributeMaxDynamicSharedMemorySize, 67840);

    dim3 pg(32, 4);   // 4096/128 x 512/128
    gemm128<<<pg, 256>>>(q_in, Wq, bq, gq, 0);
    gemm128<<<pg, 256>>>(k_in, Wk, bk, gk, 0);
    gemm128<<<pg, 256>>>(v_in, Wv, bv, gv, 0);
    attn_kernel<<<dim3(32, HH, BB), 256, 67840>>>(E, attn);
    gemm128<<<pg, 256>>>(gc, Wo, bo, out, 1);
}

// round 5
// speedup vs baseline: 1.6478x; 1.6249x over previous
#include <cuda_runtime.h>
#include <cstddef>

// Problem constants
#define BB   2
#define SS   2048
#define DD   512
#define HH   8
#define DEP  64
#define BSD  (BB*SS*DD)

// smem pitches for attn kernel
#define PQ 68     // Qs [d][q]
#define PB 196    // Bs [d][192] (K cols 0..63, E cols 64..191)
#define PV 68     // phase2 Vs/Wt pitch

// ---------------- scratch (device globals; no allocation allowed) ----------------
__device__ float g_q[BB*HH*SS*DEP];   // [B,H,S,64] projected Q
__device__ float g_k[BB*HH*SS*DEP];   // [B,H,S,64] projected K
__device__ float g_v[BB*HH*SS*DEP];   // [B,H,S,64] projected V
__device__ float g_c[BB*SS*DD];       // [B,S,D] concat(attention)

// =================================================================================
// GEMM body: out[M=4096,N=512] = X[4096,512] @ W[512,512] + bias
// mode 0: scatter to head-split layout [B,H,S,64]; mode 1: flat [M,N]
// =================================================================================
__device__ __forceinline__ void gemm_body(const float* __restrict__ X,
                                          const float* __restrict__ W,
                                          const float* __restrict__ bias,
                                          float* __restrict__ out, int mode)
{
    __shared__ float Xs[16*132];   // [k][m], padded
    __shared__ float Wt[16*132];   // [k][n], padded
    const int t  = threadIdx.x;
    const int tx = t & 15, ty = t >> 4;
    const int m0 = blockIdx.x * 128, n0 = blockIdx.y * 128;

    float acc[8][8];
    #pragma unroll
    for (int i = 0; i < 8; i++)
        #pragma unroll
        for (int j = 0; j < 8; j++) acc[i][j] = 0.f;

    for (int kb = 0; kb < DD; kb += 16) {
        __syncthreads();
        #pragma unroll
        for (int i = 0; i < 8; i++) {
            int idx = t + i*256;
            int k = idx & 15, m = idx >> 4;
            Xs[k*132 + m] = X[(size_t)(m0 + m)*DD + kb + k];
        }
        #pragma unroll
        for (int i = 0; i < 8; i++) {
            int idx = t + i*256;
            int n = idx & 127, k = idx >> 7;
            Wt[k*132 + n] = W[(size_t)(kb + k)*DD + n0 + n];
        }
        __syncthreads();
        #pragma unroll
        for (int k = 0; k < 16; k++) {
            float4 a0 = *(const float4*)&Xs[k*132 + ty*8];
            float4 a1 = *(const float4*)&Xs[k*132 + ty*8 + 4];
            float4 b0 = *(const float4*)&Wt[k*132 + tx*8];
            float4 b1 = *(const float4*)&Wt[k*132 + tx*8 + 4];
            float a[8] = {a0.x,a0.y,a0.z,a0.w,a1.x,a1.y,a1.z,a1.w};
            float b[8] = {b0.x,b0.y,b0.z,b0.w,b1.x,b1.y,b1.z,b1.w};
            #pragma unroll
            for (int i = 0; i < 8; i++)
                #pragma unroll
                for (int j = 0; j < 8; j++) acc[i][j] += a[i]*b[j];
        }
    }

    #pragma unroll
    for (int i = 0; i < 8; i++) {
        int m = m0 + ty*8 + i;
        int b_ = m >> 11, s = m & (SS - 1);
        #pragma unroll
        for (int j = 0; j < 8; j++) {
            int n = n0 + tx*8 + j;
            float v = acc[i][j] + bias[n];
            if (mode == 0) {
                int h = n >> 6, d = n & 63;
                out[(((size_t)(b_*HH + h)*SS + s) << 6) + d] = v;
            } else {
                out[(size_t)m*DD + n] = v;
            }
        }
    }
}

// Fused Q/K/V projections: blockIdx.z selects which projection. 384 CTAs.
__global__ __launch_bounds__(256) void gemm_qkv(
    const float* __restrict__ q_in, const float* __restrict__ k_in,
    const float* __restrict__ v_in,
    const float* __restrict__ Wq, const float* __restrict__ bq,
    const float* __restrict__ Wk, const float* __restrict__ bk,
    const float* __restrict__ Wv, const float* __restrict__ bv,
    float* __restrict__ gq, float* __restrict__ gk, float* __restrict__ gv)
{
    const float *X, *W, *bias; float* out;
    if (blockIdx.z == 0)      { X = q_in; W = Wq; bias = bq; out = gq; }
    else if (blockIdx.z == 1) { X = k_in; W = Wk; bias = bk; out = gk; }
    else                      { X = v_in; W = Wv; bias = bv; out = gv; }
    gemm_body(X, W, bias, out, 0);
}

__global__ __launch_bounds__(256) void gemm_out(
    const float* __restrict__ X, const float* __restrict__ W,
    const float* __restrict__ bias, float* __restrict__ out)
{
    gemm_body(X, W, bias, out, 1);
}

// =================================================================================
// Fused causal attention with relative position bias (register-tiled GEMM version).
// One CTA = (b, h, 64-query tile). 256 threads, 2 CTAs/SM.
//
// Phase 1 per 64-wide k-chunk:
//   D(64x192) = Qs(64x64) @ [K_tile ; E_window(128 rows)]^T   (4x12 reg tile/thread)
//   l[q][k] = (D[q][k] + D[q][64 + 63-q+k]) / 8, causal mask, raw l -> attn (scratch),
//   flash-style (max,sum) row stats in smem.
// Phase 2 per chunk:
//   w = exp(l - rmax)/rsum -> attn;  O += W(64x64) @ V(64x64)  (4x4 reg tile/thread)
//
// Dynamic smem (floats): Qs [d][q] 64x68 @0, Bs [d][192] pitch196 @4352
//   (phase2: Vs [k][d] 64x68 @4352, Wt [k][q] 64x68 @8704), rm @16896, rs @16960.
// Total 17024 floats = 68096 bytes.
// =================================================================================
__global__ __launch_bounds__(256, 2) void attn_kernel(const float* __restrict__ E,
                                                      float* __restrict__ attn)
{
    extern __shared__ float sm[];
    float* Qs = sm;            // [d][q] pitch PQ
    float* Bs = sm + 4352;     // [d][0..192) pitch PB ; reused as D, then Vs/Wt
    float* rm = sm + 16896;
    float* rs = sm + 16960;

    const int t  = threadIdx.x;
    const int qt = 31 - (int)blockIdx.x;   // big tiles first
    const int q0 = qt * 64;
    const int h  = blockIdx.y, b = blockIdx.z;
    const int bh = b*HH + h;
    const float* qb = g_q + (size_t)bh*SS*DEP;
    const float* kb = g_k + (size_t)bh*SS*DEP;
    const float* vb = g_v + (size_t)bh*SS*DEP;
    float* arow_base = attn + ((size_t)bh*SS + q0) * SS;

    // load Q transposed: Qs[d][i] = Q[q0+i][d]
    for (int idx = t; idx < 64*DEP; idx += 256) {
        int i = idx >> 6, d = idx & 63;
        Qs[d*PQ + i] = qb[(size_t)(q0 + i)*DEP + d];
    }
    if (t < 64) { rm[t] = -1e30f; rs[t] = 0.f; }
    __syncthreads();

    const int tx = t & 15, ty = t >> 4;    // GEMM mapping: 4 q-rows x 12 n-cols
    const int ql = t >> 2, ks4 = t & 3;    // gather/stats mapping: row ql, 16 k each
    const int nch = qt + 1;

    // ---------------- phase 1 ----------------
    for (int kt = 0; kt < nch; ++kt) {
        const int k0 = kt*64;
        // load K transposed into cols [0,64)
        for (int idx = t; idx < 64*DEP; idx += 256) {
            int i = idx >> 6, d = idx & 63;
            Bs[d*PB + i] = kb[(size_t)(k0 + i)*DEP + d];
        }
        // load E window transposed into cols [64,192)
        const int e0 = SS - 64 - q0 + k0;   // >= 0 always
        for (int idx = t; idx < 128*DEP; idx += 256) {
            int r = idx >> 6, d = idx & 63;
            int er = e0 + r;
            Bs[d*PB + 64 + r] = (er < SS) ? E[(size_t)er*DEP + d] : 0.f;
        }
        __syncthreads();

        // D = Q @ B^T : 4x12 register tile
        float acc[4][12];
        #pragma unroll
        for (int i = 0; i < 4; i++)
            #pragma unroll
            for (int j = 0; j < 12; j++) acc[i][j] = 0.f;

        const float* qcol = Qs + ty*4;
        const float* bcol = Bs + tx*12;
        #pragma unroll 8
        for (int d = 0; d < DEP; ++d) {
            float4 qv = *(const float4*)(qcol + d*PQ);
            float4 b0 = *(const float4*)(bcol + d*PB);
            float4 b1 = *(const float4*)(bcol + d*PB + 4);
            float4 b2 = *(const float4*)(bcol + d*PB + 8);
            float qa[4] = {qv.x, qv.y, qv.z, qv.w};
            float bb[12] = {b0.x,b0.y,b0.z,b0.w, b1.x,b1.y,b1.z,b1.w,
                            b2.x,b2.y,b2.z,b2.w};
            #pragma unroll
            for (int i = 0; i < 4; i++)
                #pragma unroll
                for (int j = 0; j < 12; j++) acc[i][j] += qa[i]*bb[j];
        }
        __syncthreads();

        // write D tile back into Bs (inputs no longer needed)
        #pragma unroll
        for (int i = 0; i < 4; i++) {
            float* dr = Bs + (ty*4 + i)*PB + tx*12;
            ((float4*)dr)[0] = make_float4(acc[i][0], acc[i][1], acc[i][2],  acc[i][3]);
            ((float4*)dr)[1] = make_float4(acc[i][4], acc[i][5], acc[i][6],  acc[i][7]);
            ((float4*)dr)[2] = make_float4(acc[i][8], acc[i][9], acc[i][10], acc[i][11]);
        }
        __syncthreads();

        // skew-gather + mask + stats + raw-logit store
        const float* drow = Bs + ql*PB;
        float l[16];
        float lmax = -1e30f;
        #pragma unroll
        for (int j = 0; j < 16; j++) {
            int kl = ks4 + 4*j;
            float v = drow[kl] + drow[64 + 63 - ql + kl];
            v = (k0 + kl <= q0 + ql) ? v*0.125f : -1e30f;
            l[j] = v;
            lmax = fmaxf(lmax, v);
        }
        float lsum = 0.f;
        #pragma unroll
        for (int j = 0; j < 16; j++) lsum += __expf(l[j] - lmax);

        float* ar = arow_base + (size_t)ql*SS + k0;
        #pragma unroll
        for (int j = 0; j < 16; j++) ar[ks4 + 4*j] = l[j];

        #pragma unroll
        for (int off = 1; off < 4; off <<= 1) {
            float om = __shfl_xor_sync(0xffffffffu, lmax, off);
            float os = __shfl_xor_sync(0xffffffffu, lsum, off);
            float nm = fmaxf(lmax, om);
            lsum = lsum*__expf(lmax - nm) + os*__expf(om - nm);
            lmax = nm;
        }
        if (ks4 == 0) {
            float mo = rm[ql];
            float nm = fmaxf(mo, lmax);
            rs[ql] = rs[ql]*__expf(mo - nm) + lsum*__expf(lmax - nm);
            rm[ql] = nm;
        }
        __syncthreads();
    }

    const float rmax = rm[ql];
    const float rinv = 1.f / rs[ql];

    // ---------------- phase 2: normalize + O = W @ V ----------------
    float* Vs = Bs;           // [k][d] pitch PV
    float* Wt = Bs + 4352;    // [k][q] pitch PV
    float Ov[4][4];
    #pragma unroll
    for (int i = 0; i < 4; i++)
        #pragma unroll
        for (int j = 0; j < 4; j++) Ov[i][j] = 0.f;

    for (int kt = 0; kt < nch; ++kt) {
        const int k0 = kt*64;
        __syncthreads();   // previous-iteration Vs/Wt reads complete
        for (int idx = t; idx < 64*DEP; idx += 256) {
            int i = idx >> 6, d = idx & 63;
            Vs[i*PV + d] = vb[(size_t)(k0 + i)*DEP + d];
        }
        float* ar = arow_base + (size_t)ql*SS + k0;
        #pragma unroll
        for (int j = 0; j < 16; j++) {
            int kl = ks4 + 4*j;
            float w = __expf(ar[kl] - rmax) * rinv;   // masked -> exact 0
            ar[kl] = w;
            Wt[kl*PV + ql] = w;
        }
        __syncthreads();
        #pragma unroll 4
        for (int kk = 0; kk < 64; ++kk) {
            float4 wv = *(const float4*)(Wt + kk*PV + ty*4);
            float4 vv = *(const float4*)(Vs + kk*PV + tx*4);
            float wa[4] = {wv.x, wv.y, wv.z, wv.w};
            float va[4] = {vv.x, vv.y, vv.z, vv.w};
            #pragma unroll
            for (int i = 0; i < 4; i++)
                #pragma unroll
                for (int j = 0; j < 4; j++) Ov[i][j] += wa[i]*va[j];
        }
    }

    // zero-fill strictly-upper tail columns [nch*64, S)
    const int kstart = nch*64;
    if (kstart < SS) {
        const int len4 = (SS - kstart) >> 2;
        const int tot = 64 * len4;
        for (int idx = t; idx < tot; idx += 256) {
            int row = idx / len4, c = idx - row*len4;
            ((float4*)(arow_base + (size_t)row*SS + kstart))[c] =
                make_float4(0.f, 0.f, 0.f, 0.f);
        }
    }

    // O -> concat buffer [B,S,D]
    #pragma unroll
    for (int i = 0; i < 4; i++) {
        float* cr = g_c + ((size_t)b*SS + q0 + ty*4 + i)*DD + h*64 + tx*4;
        *(float4*)cr = make_float4(Ov[i][0], Ov[i][1], Ov[i][2], Ov[i][3]);
    }
}

// =================================================================================
// launch
// inputs: 0 v_in, 1 k_in, 2 q_in, 3 mask(unused), 4 Wq, 5 bq, 6 Wk, 7 bk,
//         8 Wv, 9 bv, 10 Wo, 11 bo, 12 E
// output: [output (B*S*D floats)] ++ [attention_weights (B*H*S*S floats)]
// =================================================================================
extern "C" void kernel_launch(void* const* d_in, const int* in_sizes, int n_in,
                              void* d_out, int out_size)
{
    (void)in_sizes; (void)n_in; (void)out_size;
    const float* v_in = (const float*)d_in[0];
    const float* k_in = (const float*)d_in[1];
    const float* q_in = (const float*)d_in[2];
    const float* Wq   = (const float*)d_in[4];
    const float* bq   = (const float*)d_in[5];
    const float* Wk   = (const float*)d_in[6];
    const float* bk   = (const float*)d_in[7];
    const float* Wv   = (const float*)d_in[8];
    const float* bv   = (const float*)d_in[9];
    const float* Wo   = (const float*)d_in[10];
    const float* bo   = (const float*)d_in[11];
    const float* E    = (const float*)d_in[12];

    float* out  = (float*)d_out;
    float* attn = out + (size_t)BSD;

    float *gq, *gk, *gv, *gc;
    cudaGetSymbolAddress((void**)&gq, g_q);
    cudaGetSymbolAddress((void**)&gk, g_k);
    cudaGetSymbolAddress((void**)&gv, g_v);
    cudaGetSymbolAddress((void**)&gc, g_c);

    cudaFuncSetAttribute(attn_kernel,
                         cudaFuncAttributeMaxDynamicSharedMemorySize, 68096);

    gemm_qkv<<<dim3(32, 4, 3), 256>>>(q_in, k_in, v_in,
                                      Wq, bq, Wk, bk, Wv, bv,
                                      gq, gk, gv);
    attn_kernel<<<dim3(32, HH, BB), 256, 68096>>>(E, attn);
    gemm_out<<<dim3(32, 4), 256>>>(gc, Wo, bo, out);
}

// round 6
// speedup vs baseline: 1.6784x; 1.0186x over previous
#include <cuda_runtime.h>
#include <cstddef>

// Problem constants
#define BB   2
#define SS   2048
#define DD   512
#define HH   8
#define DEP  64
#define BSD  (BB*SS*DD)

// attn smem pitches
#define PQ 68     // Qs [d][q]
#define PB 132    // Bs [d][0..128): K cols 0-63, E-new cols 64-127
#define PD 68     // DK [q][k]
#define PE 132    // DE ring [q][slot 0..127]
#define PV 68     // phase2 Vs/Wt pitch

// smem offsets (floats)
#define OFF_QS 0
#define OFF_BS 4352      // 64*68
#define OFF_DK 12800     // OFF_BS + 64*132
#define OFF_DE 17152     // OFF_DK + 64*68
#define OFF_RM 25600     // OFF_DE + 64*132
#define OFF_RS 25664
#define SMEM_FLOATS 25728
#define SMEM_BYTES  (SMEM_FLOATS*4)   // 102912

// ---------------- scratch (device globals; no allocation allowed) ----------------
__device__ float g_q[BB*HH*SS*DEP];   // [B,H,S,64] projected Q
__device__ float g_k[BB*HH*SS*DEP];   // [B,H,S,64] projected K
__device__ float g_v[BB*HH*SS*DEP];   // [B,H,S,64] projected V
__device__ float g_c[BB*SS*DD];       // [B,S,D] concat(attention)

// =================================================================================
// GEMM body: out[M=4096,N=512] = X[4096,512] @ W[512,512] + bias
// mode 0: scatter to head-split layout [B,H,S,64]; mode 1: flat [M,N]
// =================================================================================
__device__ __forceinline__ void gemm_body(const float* __restrict__ X,
                                          const float* __restrict__ W,
                                          const float* __restrict__ bias,
                                          float* __restrict__ out, int mode)
{
    __shared__ float Xs[16*132];   // [k][m], padded
    __shared__ float Wt[16*132];   // [k][n], padded
    const int t  = threadIdx.x;
    const int tx = t & 15, ty = t >> 4;
    const int m0 = blockIdx.x * 128, n0 = blockIdx.y * 128;

    float acc[8][8];
    #pragma unroll
    for (int i = 0; i < 8; i++)
        #pragma unroll
        for (int j = 0; j < 8; j++) acc[i][j] = 0.f;

    for (int kb = 0; kb < DD; kb += 16) {
        __syncthreads();
        #pragma unroll
        for (int i = 0; i < 8; i++) {
            int idx = t + i*256;
            int k = idx & 15, m = idx >> 4;
            Xs[k*132 + m] = X[(size_t)(m0 + m)*DD + kb + k];
        }
        #pragma unroll
        for (int i = 0; i < 8; i++) {
            int idx = t + i*256;
            int n = idx & 127, k = idx >> 7;
            Wt[k*132 + n] = W[(size_t)(kb + k)*DD + n0 + n];
        }
        __syncthreads();
        #pragma unroll
        for (int k = 0; k < 16; k++) {
            float4 a0 = *(const float4*)&Xs[k*132 + ty*8];
            float4 a1 = *(const float4*)&Xs[k*132 + ty*8 + 4];
            float4 b0 = *(const float4*)&Wt[k*132 + tx*8];
            float4 b1 = *(const float4*)&Wt[k*132 + tx*8 + 4];
            float a[8] = {a0.x,a0.y,a0.z,a0.w,a1.x,a1.y,a1.z,a1.w};
            float b[8] = {b0.x,b0.y,b0.z,b0.w,b1.x,b1.y,b1.z,b1.w};
            #pragma unroll
            for (int i = 0; i < 8; i++)
                #pragma unroll
                for (int j = 0; j < 8; j++) acc[i][j] += a[i]*b[j];
        }
    }

    #pragma unroll
    for (int i = 0; i < 8; i++) {
        int m = m0 + ty*8 + i;
        int b_ = m >> 11, s = m & (SS - 1);
        #pragma unroll
        for (int j = 0; j < 8; j++) {
            int n = n0 + tx*8 + j;
            float v = acc[i][j] + bias[n];
            if (mode == 0) {
                int h = n >> 6, d = n & 63;
                out[(((size_t)(b_*HH + h)*SS + s) << 6) + d] = v;
            } else {
                out[(size_t)m*DD + n] = v;
            }
        }
    }
}

// Fused Q/K/V projections: blockIdx.z selects which projection. 384 CTAs.
__global__ __launch_bounds__(256, 2) void gemm_qkv(
    const float* __restrict__ q_in, const float* __restrict__ k_in,
    const float* __restrict__ v_in,
    const float* __restrict__ Wq, const float* __restrict__ bq,
    const float* __restrict__ Wk, const float* __restrict__ bk,
    const float* __restrict__ Wv, const float* __restrict__ bv,
    float* __restrict__ gq, float* __restrict__ gk, float* __restrict__ gv)
{
    const float *X, *W, *bias; float* out;
    if (blockIdx.z == 0)      { X = q_in; W = Wq; bias = bq; out = gq; }
    else if (blockIdx.z == 1) { X = k_in; W = Wk; bias = bk; out = gk; }
    else                      { X = v_in; W = Wv; bias = bv; out = gv; }
    gemm_body(X, W, bias, out, 0);
}

__global__ __launch_bounds__(256, 2) void gemm_out(
    const float* __restrict__ X, const float* __restrict__ W,
    const float* __restrict__ bias, float* __restrict__ out)
{
    gemm_body(X, W, bias, out, 1);
}

// =================================================================================
// Fused causal attention with relative position bias — rolling-E version.
//
// Key idea: the Q.E dot products for chunk kt need E-window rows e0+[0,128),
// but consecutive chunks overlap by 64 rows. Keep a 64x128 ring buffer DE of
// Q.E dots in smem; each chunk computes only the 64 NEW rows (prologue computes
// the initial 64). Phase-1 GEMM per chunk shrinks 64x192 -> 64x128 (-33% FLOPs
// and smem traffic).
//
//   DE slot for E-row offset `off` at chunk kt: (64*kt + off) & 127,
//   off = 63 - ql + kl.  Rows with er >= S feed only causally-masked entries.
//
// smem (floats): Qs[64x68]@0, Bs[64x132]@4352 (K cols 0-63, Enew cols 64-127),
//   DK[64x68]@12800, DE[64x132]@17152, rm@25600, rs@25664.  102912 bytes.
//   Phase 2 reuses [4352,13056): Vs@4352 (64x68), Wt@8704 (64x68).
// 2 CTAs/SM (205.8KB <= 228KB).
// =================================================================================
__global__ __launch_bounds__(256, 2) void attn_kernel(const float* __restrict__ E,
                                                      float* __restrict__ attn)
{
    extern __shared__ float sm[];
    float* Qs = sm + OFF_QS;
    float* Bs = sm + OFF_BS;
    float* DK = sm + OFF_DK;
    float* DE = sm + OFF_DE;
    float* rm = sm + OFF_RM;
    float* rs = sm + OFF_RS;

    const int t  = threadIdx.x;
    const int qt = 31 - (int)blockIdx.x;   // big tiles first
    const int q0 = qt * 64;
    const int h  = blockIdx.y, b = blockIdx.z;
    const int bh = b*HH + h;
    const float* qb = g_q + (size_t)bh*SS*DEP;
    const float* kb = g_k + (size_t)bh*SS*DEP;
    const float* vb = g_v + (size_t)bh*SS*DEP;
    float* arow_base = attn + ((size_t)bh*SS + q0) * SS;

    // load Q transposed: Qs[d][i] = Q[q0+i][d]
    for (int idx = t; idx < 64*DEP; idx += 256) {
        int i = idx >> 6, d = idx & 63;
        Qs[d*PQ + i] = qb[(size_t)(q0 + i)*DEP + d];
    }
    // prologue E rows: er0 + [0,64), er0 = S-64-q0 (always in range)
    {
        const int er0 = SS - 64 - q0;
        for (int idx = t; idx < 64*DEP; idx += 256) {
            int r = idx >> 6, d = idx & 63;
            Bs[d*PB + r] = E[(size_t)(er0 + r)*DEP + d];
        }
    }
    if (t < 64) { rm[t] = -1e30f; rs[t] = 0.f; }
    __syncthreads();

    const int ql = t >> 2, ks4 = t & 3;    // gather/stats mapping
    const int nch = qt + 1;

    // ---------------- prologue GEMM: DE slots [0,64) ----------------
    {
        const int rg = t >> 4, cg = t & 15;   // 4 rows x 4 cols per thread
        float acc[4][4];
        #pragma unroll
        for (int i = 0; i < 4; i++)
            #pragma unroll
            for (int j = 0; j < 4; j++) acc[i][j] = 0.f;
        const float* qcol = Qs + rg*4;
        const float* bcol = Bs + cg*4;
        #pragma unroll 4
        for (int d = 0; d < DEP; ++d) {
            float4 qv = *(const float4*)(qcol + d*PQ);
            float4 bv = *(const float4*)(bcol + d*PB);
            float qa[4] = {qv.x,qv.y,qv.z,qv.w};
            float ba[4] = {bv.x,bv.y,bv.z,bv.w};
            #pragma unroll
            for (int i = 0; i < 4; i++)
                #pragma unroll
                for (int j = 0; j < 4; j++) acc[i][j] += qa[i]*ba[j];
        }
        #pragma unroll
        for (int i = 0; i < 4; i++)
            *(float4*)(DE + (rg*4 + i)*PE + cg*4) =
                make_float4(acc[i][0], acc[i][1], acc[i][2], acc[i][3]);
    }
    __syncthreads();

    // ---------------- phase 1 main loop ----------------
    const int rg = t >> 4, cg = t & 15;   // GEMM: 4 rows x 8 cols per thread
    for (int kt = 0; kt < nch; ++kt) {
        const int k0 = kt*64;
        // load K transposed into cols [0,64)
        for (int idx = t; idx < 64*DEP; idx += 256) {
            int i = idx >> 6, d = idx & 63;
            Bs[d*PB + i] = kb[(size_t)(k0 + i)*DEP + d];
        }
        // load NEW E rows (er = S - q0 + 64*kt + r) into cols [64,128)
        {
            const int ern = SS - q0 + 64*kt;
            for (int idx = t; idx < 64*DEP; idx += 256) {
                int r = idx >> 6, d = idx & 63;
                int er = ern + r;
                Bs[d*PB + 64 + r] = (er < SS) ? E[(size_t)er*DEP + d] : 0.f;
            }
        }
        __syncthreads();

        // GEMM 64x128: acc 4x8 per thread
        float acc[4][8];
        #pragma unroll
        for (int i = 0; i < 4; i++)
            #pragma unroll
            for (int j = 0; j < 8; j++) acc[i][j] = 0.f;
        const float* qcol = Qs + rg*4;
        const float* bcol = Bs + cg*8;
        #pragma unroll 4
        for (int d = 0; d < DEP; ++d) {
            float4 qv = *(const float4*)(qcol + d*PQ);
            float4 b0 = *(const float4*)(bcol + d*PB);
            float4 b1 = *(const float4*)(bcol + d*PB + 4);
            float qa[4] = {qv.x,qv.y,qv.z,qv.w};
            float bb[8] = {b0.x,b0.y,b0.z,b0.w, b1.x,b1.y,b1.z,b1.w};
            #pragma unroll
            for (int i = 0; i < 4; i++)
                #pragma unroll
                for (int j = 0; j < 8; j++) acc[i][j] += qa[i]*bb[j];
        }

        // writeback: cg<8 -> DK, cg>=8 -> DE new slots
        if (cg < 8) {
            #pragma unroll
            for (int i = 0; i < 4; i++) {
                float* dr = DK + (rg*4 + i)*PD + cg*8;
                ((float4*)dr)[0] = make_float4(acc[i][0], acc[i][1], acc[i][2], acc[i][3]);
                ((float4*)dr)[1] = make_float4(acc[i][4], acc[i][5], acc[i][6], acc[i][7]);
            }
        } else {
            const int sb = (64*(kt + 1)) & 127;      // new-slot base (0 or 64)
            const int c0 = sb + (cg - 8)*8;
            #pragma unroll
            for (int i = 0; i < 4; i++) {
                float* dr = DE + (rg*4 + i)*PE + c0;
                ((float4*)dr)[0] = make_float4(acc[i][0], acc[i][1], acc[i][2], acc[i][3]);
                ((float4*)dr)[1] = make_float4(acc[i][4], acc[i][5], acc[i][6], acc[i][7]);
            }
        }
        __syncthreads();

        // skew-gather + mask + stats + raw-logit store
        const float* dkr = DK + ql*PD;
        const float* der = DE + ql*PE;
        const int slotbase = 64*kt + 63 - ql;   // >= 0
        float l[16];
        float lmax = -1e30f;
        #pragma unroll
        for (int j = 0; j < 16; j++) {
            int kl = ks4 + 4*j;
            float v = dkr[kl] + der[(slotbase + kl) & 127];
            v = (k0 + kl <= q0 + ql) ? v*0.125f : -1e30f;
            l[j] = v;
            lmax = fmaxf(lmax, v);
        }
        float lsum = 0.f;
        #pragma unroll
        for (int j = 0; j < 16; j++) lsum += __expf(l[j] - lmax);

        float* ar = arow_base + (size_t)ql*SS + k0;
        #pragma unroll
        for (int j = 0; j < 16; j++) ar[ks4 + 4*j] = l[j];

        #pragma unroll
        for (int off = 1; off < 4; off <<= 1) {
            float om = __shfl_xor_sync(0xffffffffu, lmax, off);
            float os = __shfl_xor_sync(0xffffffffu, lsum, off);
            float nm = fmaxf(lmax, om);
            lsum = lsum*__expf(lmax - nm) + os*__expf(om - nm);
            lmax = nm;
        }
        if (ks4 == 0) {
            float mo = rm[ql];
            float nm = fmaxf(mo, lmax);
            rs[ql] = rs[ql]*__expf(mo - nm) + lsum*__expf(lmax - nm);
            rm[ql] = nm;
        }
        __syncthreads();   // rm/rs visible; DK/DE reads done before next writeback
    }

    const float rmax = rm[ql];
    const float rinv = 1.f / rs[ql];

    // ---------------- phase 2: normalize + O = W @ V ----------------
    const int tx = t & 15, ty = t >> 4;    // 4x4 tile per thread
    float* Vs = sm + OFF_BS;               // [k][d] pitch PV
    float* Wt = sm + OFF_BS + 4352;        // [k][q] pitch PV
    float Ov[4][4];
    #pragma unroll
    for (int i = 0; i < 4; i++)
        #pragma unroll
        for (int j = 0; j < 4; j++) Ov[i][j] = 0.f;

    for (int kt = 0; kt < nch; ++kt) {
        const int k0 = kt*64;
        __syncthreads();   // previous-iteration Vs/Wt reads complete
        for (int idx = t; idx < 64*DEP; idx += 256) {
            int i = idx >> 6, d = idx & 63;
            Vs[i*PV + d] = vb[(size_t)(k0 + i)*DEP + d];
        }
        float* ar = arow_base + (size_t)ql*SS + k0;
        #pragma unroll
        for (int j = 0; j < 16; j++) {
            int kl = ks4 + 4*j;
            float w = __expf(ar[kl] - rmax) * rinv;   // masked -> exact 0
            ar[kl] = w;
            Wt[kl*PV + ql] = w;
        }
        __syncthreads();
        #pragma unroll 4
        for (int kk = 0; kk < 64; ++kk) {
            float4 wv = *(const float4*)(Wt + kk*PV + ty*4);
            float4 vv = *(const float4*)(Vs + kk*PV + tx*4);
            float wa[4] = {wv.x, wv.y, wv.z, wv.w};
            float va[4] = {vv.x, vv.y, vv.z, vv.w};
            #pragma unroll
            for (int i = 0; i < 4; i++)
                #pragma unroll
                for (int j = 0; j < 4; j++) Ov[i][j] += wa[i]*va[j];
        }
    }

    // zero-fill strictly-upper tail columns [nch*64, S)
    const int kstart = nch*64;
    if (kstart < SS) {
        const int len4 = (SS - kstart) >> 2;
        const int tot = 64 * len4;
        for (int idx = t; idx < tot; idx += 256) {
            int row = idx / len4, c = idx - row*len4;
            ((float4*)(arow_base + (size_t)row*SS + kstart))[c] =
                make_float4(0.f, 0.f, 0.f, 0.f);
        }
    }

    // O -> concat buffer [B,S,D]
    #pragma unroll
    for (int i = 0; i < 4; i++) {
        float* cr = g_c + ((size_t)b*SS + q0 + ty*4 + i)*DD + h*64 + tx*4;
        *(float4*)cr = make_float4(Ov[i][0], Ov[i][1], Ov[i][2], Ov[i][3]);
    }
}

// =================================================================================
// launch
// inputs: 0 v_in, 1 k_in, 2 q_in, 3 mask(unused), 4 Wq, 5 bq, 6 Wk, 7 bk,
//         8 Wv, 9 bv, 10 Wo, 11 bo, 12 E
// output: [output (B*S*D floats)] ++ [attention_weights (B*H*S*S floats)]
// =================================================================================
extern "C" void kernel_launch(void* const* d_in, const int* in_sizes, int n_in,
                              void* d_out, int out_size)
{
    (void)in_sizes; (void)n_in; (void)out_size;
    const float* v_in = (const float*)d_in[0];
    const float* k_in = (const float*)d_in[1];
    const float* q_in = (const float*)d_in[2];
    const float* Wq   = (const float*)d_in[4];
    const float* bq   = (const float*)d_in[5];
    const float* Wk   = (const float*)d_in[6];
    const float* bk   = (const float*)d_in[7];
    const float* Wv   = (const float*)d_in[8];
    const float* bv   = (const float*)d_in[9];
    const float* Wo   = (const float*)d_in[10];
    const float* bo   = (const float*)d_in[11];
    const float* E    = (const float*)d_in[12];

    float* out  = (float*)d_out;
    float* attn = out + (size_t)BSD;

    float *gq, *gk, *gv, *gc;
    cudaGetSymbolAddress((void**)&gq, g_q);
    cudaGetSymbolAddress((void**)&gk, g_k);
    cudaGetSymbolAddress((void**)&gv, g_v);
    cudaGetSymbolAddress((void**)&gc, g_c);

    cudaFuncSetAttribute(attn_kernel,
                         cudaFuncAttributeMaxDynamicSharedMemorySize, SMEM_BYTES);

    gemm_qkv<<<dim3(32, 4, 3), 256>>>(q_in, k_in, v_in,
                                      Wq, bq, Wk, bk, Wv, bv,
                                      gq, gk, gv);
    attn_kernel<<<dim3(32, HH, BB), 256, SMEM_BYTES>>>(E, attn);
    gemm_out<<<dim3(32, 4), 256>>>(gc, Wo, bo, out);
}